// round 16
// baseline (speedup 1.0000x reference)
#include <cuda_runtime.h>
#include <cuda_fp16.h>
#include <cstdint>
#include <cstddef>

// NeRD pixel decoder — fp16 mma.sync m16n8k16, ldmatrix.x4, K=64 slabs,
// WARP-SPECIALIZED: 8 consumer warps (64x64 tiles, pure LDSM+HMMA) + 2
// producer warps (all cp.async staging), decoupled by named barriers:
//   R_i (id 1+i): buffer i slab ready — producer arrives, consumers sync
//   F_i (id 4+i): buffer i free      — consumers arrive, producer syncs
//   id 7: consumer-only full sync (epilogues)
// Consumers may drift up to 3 slabs apart -> cross-warp latency hiding
// without extra crossbar traffic. Producer uses empty commit_group trick so
// wait_group 2 always means "slab s staged".
// Slab stream: s=0..49 layer0 (25 taps x 2 ch-halves), 50..53 W1, 54..57 W2.
// Weights pre-scaled by 2^8 (exact); epilogue multiplies acc by 2^-8.

#define FC   128
#define HID  256
#define OUTC 3
#define IMH  128
#define IMW  128
#define OMEGA 30.0f
#define THREADS 320
#define WSCALE 256.0f
#define INV_WSCALE 0.00390625f

#define SMH_H 264
#define SMA_H 72
#define SMB_H 72
#define SMH_HALF (128 * SMH_H)      // 33792
#define SMA_HALF (132 * SMA_H)      // 9504 (x2 alias into smH region)
#define SMB_HALF (256 * SMB_H)      // 18432
#define SMEM_BYTES ((SMH_HALF + 3 * SMB_HALF) * 2)   // 178176 B

__device__ __half g_xiA[2 * 2 * 132 * 132 * 64];   // [((b*2+ch)*132+hp)][wa*64+kc]
__device__ __half g_W0s[25 * 2 * 256 * 64];        // [(tap*2+ch)*256+n][kc] *2^8
__device__ __half g_W1s[4 * 256 * 64];             // [(kb*256+n)][kc]      *2^8
__device__ __half g_W2s[4 * 256 * 64];

__device__ __forceinline__ void mma16(float* c, const unsigned* a, unsigned b0, unsigned b1) {
    asm("mma.sync.aligned.m16n8k16.row.col.f32.f16.f16.f32 "
        "{%0,%1,%2,%3}, {%4,%5,%6,%7}, {%8,%9}, {%0,%1,%2,%3};"
        : "+f"(c[0]), "+f"(c[1]), "+f"(c[2]), "+f"(c[3])
        : "r"(a[0]), "r"(a[1]), "r"(a[2]), "r"(a[3]), "r"(b0), "r"(b1));
}

__device__ __forceinline__ void ldsm4(unsigned& r0, unsigned& r1, unsigned& r2,
                                      unsigned& r3, unsigned addr) {
    asm volatile("ldmatrix.sync.aligned.m8n8.x4.shared.b16 {%0,%1,%2,%3}, [%4];"
                 : "=r"(r0), "=r"(r1), "=r"(r2), "=r"(r3) : "r"(addr));
}

__device__ __forceinline__ void cpa16(unsigned dst, const void* src) {
    asm volatile("cp.async.ca.shared.global [%0], [%1], 16;" :: "r"(dst), "l"(src));
}
#define CP_COMMIT asm volatile("cp.async.commit_group;" ::: "memory")
#define CP_WAIT(n) asm volatile("cp.async.wait_group %0;" :: "n"(n) : "memory")
#define NBAR_SYNC(id, cnt)   asm volatile("bar.sync %0, %1;"   :: "r"(id), "r"(cnt) : "memory")
#define NBAR_ARRIVE(id, cnt) asm volatile("bar.arrive %0, %1;" :: "r"(id), "r"(cnt) : "memory")

// ================= fused prep kernel (256 threads; layouts as R12) =========
#define XI_BLOCKS 528
extern "C" __global__ void prep_kernel(const float* __restrict__ xi,
                                       const float* __restrict__ W0,
                                       const float* __restrict__ W1,
                                       const float* __restrict__ W2) {
    const int tid = threadIdx.x;
    if (blockIdx.x < XI_BLOCKS) {
        __shared__ __half smT[64][134];
        const int bi = blockIdx.x;
        const int hp = bi % 132;
        const int t  = bi / 132;
        const int ch = t & 1, b = t >> 1;
        const int h  = hp - 2;
        const bool hok = (unsigned)h < IMH;
        if (tid < 64) {
            smT[tid][0] = __half(0); smT[tid][1] = __half(0);
            smT[tid][130] = __half(0); smT[tid][131] = __half(0);
        }
        const int w = tid & 127, cl0 = tid >> 7;
        for (int cc = 0; cc < 64; cc += 2) {
            const int cl = cc + cl0;
            float v = 0.f;
            if (hok)
                v = xi[(((size_t)b * FC + ch * 64 + cl) * IMH + h) * IMW + w];
            smT[cl][w + 2] = __float2half_rn(v);
        }
        __syncthreads();
        __half2* dst2 = (__half2*)(g_xiA + ((size_t)bi) * (132 * 64));
        for (int r2 = tid; r2 < 132 * 32; r2 += 256) {
            const int kc2 = r2 & 31, wa = r2 >> 5;
            dst2[r2] = __halves2half2(smT[2 * kc2][wa], smT[2 * kc2 + 1][wa]);
        }
    } else {
        const int base = (blockIdx.x - XI_BLOCKS) * 2048;
        const int NW0 = 25 * 2 * 256 * 64;
#pragma unroll
        for (int l = 0; l < 8; ++l) {
            const int idx = base + l * 256 + tid;
            if (idx < NW0) {
                const int kc = idx & 63, n = (idx >> 6) & 255;
                const int ch = (idx >> 14) & 1, tap = idx >> 15;
                const int c = ch * 64 + kc;
                g_W0s[idx] = __float2half_rn(W0[((size_t)c * 25 + tap) * HID + n] * WSCALE);
            } else {
                int r = idx - NW0;
                if (r < 2 * 65536) {
                    const int which = r >> 16; r &= 65535;
                    const int kc = r & 63, n = (r >> 6) & 255, kb = r >> 14;
                    const int k = kb * 64 + kc;
                    const float v = (which ? W2 : W1)[(size_t)k * HID + n] * WSCALE;
                    if (which) g_W2s[r] = __float2half_rn(v);
                    else       g_W1s[r] = __float2half_rn(v);
                }
            }
        }
    }
}

// ================= main fused kernel =================
extern "C" __global__ void __launch_bounds__(THREADS, 1)
nerd_fused_kernel(const float* __restrict__ W0f, const float* __restrict__ b0,
                  const float* __restrict__ b1, const float* __restrict__ b2,
                  const float* __restrict__ W3, const float* __restrict__ b3,
                  float* __restrict__ out)
{
    extern __shared__ __half smem[];
    __half* smH = smem;                              // [128][264]
    const unsigned sbase = (unsigned)__cvta_generic_to_shared(smem);

    const int tid  = threadIdx.x;
    const int lane = tid & 31, warp = tid >> 5;      // 10 warps: 8 cons + 2 prod
    const int bx = blockIdx.x, bimg = bx >> 7, hrow = bx & 127;

#define BBUF(r) (sbase + (SMH_HALF + (r) * SMB_HALF) * 2)

    if (warp >= 8) {
        // ======================= PRODUCER (warps 8,9) ========================
        const int ptid = tid - 256;                  // 0..63
        auto stB = [&](const __half* src, unsigned bufB) {
#pragma unroll
            for (int l = 0; l < 32; ++l) {
                const int idx = ptid + l * 64;
                cpa16(bufB + ((idx >> 3) * SMB_H + (idx & 7) * 8) * 2,
                      src + (size_t)idx * 8);
            }
        };
        auto stA = [&](const __half* src, unsigned bufB) {
#pragma unroll
            for (int l = 0; l < 17; ++l) {
                const int idx = ptid + l * 64;
                if (idx < 1056)
                    cpa16(bufB + ((idx >> 3) * SMA_H + (idx & 7) * 8) * 2,
                          src + (size_t)idx * 8);
            }
        };
        auto aSrcP = [&](int g) {                    // g = ph*2 + ch
            const int ph = g >> 1, ch = g & 1;
            return g_xiA + ((size_t)((bimg * 2 + ch) * 132 + hrow + ph)) * (132 * 64);
        };
        auto bSrc = [&](int s) -> const __half* {
            if (s < 50) {
                const int g = s / 5, pw = s - g * 5;
                const int ph = g >> 1, ch = g & 1;
                return g_W0s + ((size_t)((ph * 5 + pw) * 2 + ch)) * 16384;
            } else if (s < 54) return g_W1s + (size_t)(s - 50) * 16384;
            else               return g_W2s + (size_t)(s - 54) * 16384;
        };

        // prologue: slabs 0 (with A(0)), 1, 2
        stA(aSrcP(0), sbase);
        stB(bSrc(0), BBUF(0)); CP_COMMIT;
        stB(bSrc(1), BBUF(1)); CP_COMMIT;
        stB(bSrc(2), BBUF(2)); CP_COMMIT;

        int rR = 0;
        for (int s = 0; s < 58; ++s) {
            CP_WAIT(2);                              // slab s group complete
            NBAR_ARRIVE(1 + rR, 320);                // ready
            const int t = s + 3;
            if (t < 58) {
                NBAR_SYNC(4 + rR, 320);              // consumers past slab s
                stB(bSrc(t), BBUF(rR));
                if (t < 50 && (t % 5) == 3) {
                    const int gn = t / 5 + 1;
                    if (gn < 10)
                        stA(aSrcP(gn), sbase + ((gn & 1) * SMA_HALF) * 2);
                }
            }
            CP_COMMIT;                               // real or empty group
            rR = (rR == 2) ? 0 : rR + 1;
        }
        return;                                      // producers exit
    }

    // ========================= CONSUMER (warps 0..7) =========================
    const int wm = warp >> 2, wn = warp & 3;         // 2 x 4 grid, tile 64x64
    const int lr = lane >> 2, lc = lane & 3;
    const int l15 = lane & 15, lhi = lane >> 4;

    float acc[128];
#pragma unroll
    for (int i = 0; i < 128; ++i) acc[i] = 0.f;

    unsigned aRow[4], bRow[4], aRowH[4];
#pragma unroll
    for (int mt = 0; mt < 4; ++mt) {
        aRow[mt]  = ((wm * 64 + mt * 16 + l15) * SMA_H + lhi * 8) * 2;
        aRowH[mt] = sbase + ((wm * 64 + mt * 16 + l15) * SMH_H + lhi * 8) * 2;
    }
#pragma unroll
    for (int np = 0; np < 4; ++np)
        bRow[np] = ((wn * 64 + np * 16 + l15) * SMB_H + lhi * 8) * 2;

    unsigned af[4][4], bf[2][4];

#define MMA_SLAB() do {                                                        \
    _Pragma("unroll") for (int kk = 0; kk < 4; ++kk) {                         \
        _Pragma("unroll") for (int mt = 0; mt < 4; ++mt)                       \
            ldsm4(af[mt][0], af[mt][1], af[mt][2], af[mt][3],                  \
                  aAd[mt] + kk * 32);                                          \
        ldsm4(bf[0][0], bf[0][1], bf[0][2], bf[0][3], bAd[0] + kk * 32);       \
        _Pragma("unroll") for (int np = 0; np < 4; ++np) {                     \
            if (np < 3) {                                                      \
                const int nb = (np + 1) & 1;                                   \
                ldsm4(bf[nb][0], bf[nb][1], bf[nb][2], bf[nb][3],              \
                      bAd[np + 1] + kk * 32);                                  \
            }                                                                  \
            const int cu = np & 1;                                             \
            _Pragma("unroll") for (int mt = 0; mt < 4; ++mt) {                 \
                mma16(&acc[(mt * 8 + 2 * np) * 4],     af[mt], bf[cu][0], bf[cu][2]); \
                mma16(&acc[(mt * 8 + 2 * np + 1) * 4], af[mt], bf[cu][1], bf[cu][3]); \
            }                                                                  \
        }                                                                      \
    } } while (0)

    int rR = 0;
    // ================= Layer 0: slabs 0..49 =================
    for (int g = 0; g < 10; ++g) {
        const unsigned aBufB = sbase + (g & 1) * (SMA_HALF * 2);
#pragma unroll 1
        for (int pw = 0; pw < 5; ++pw) {
            NBAR_SYNC(1 + rR, 320);                  // slab ready
            unsigned aAd[4], bAd[4];
            const unsigned aPw = aBufB + pw * (SMA_H * 2);
            const unsigned bBufB = BBUF(rR);
#pragma unroll
            for (int mt = 0; mt < 4; ++mt) aAd[mt] = aPw + aRow[mt];
#pragma unroll
            for (int np = 0; np < 4; ++np) bAd[np] = bBufB + bRow[np];
            MMA_SLAB();
            NBAR_ARRIVE(4 + rR, 320);                // buffer free
            rR = (rR == 2) ? 0 : rR + 1;
        }
    }

    // ---- layer-0 epilogue ----
    NBAR_SYNC(7, 256);                               // all consumers past L0 reads
    {
        const float gy = -1.f + 2.f * (float)hrow * (1.f / 127.f);
#pragma unroll
        for (int mt = 0; mt < 4; ++mt)
#pragma unroll
            for (int nt = 0; nt < 8; ++nt)
#pragma unroll
                for (int hf = 0; hf < 2; ++hf) {
                    const int m = wm * 64 + mt * 16 + lr + hf * 8;
                    const int n0 = wn * 64 + nt * 8 + lc * 2;
                    const float gx = -1.f + 2.f * (float)m * (1.f / 127.f);
                    const float z0 = acc[(mt * 8 + nt) * 4 + hf * 2 + 0] * INV_WSCALE
                                   + gx * W0f[3200 * HID + n0] + gy * W0f[3201 * HID + n0] + b0[n0];
                    const float z1 = acc[(mt * 8 + nt) * 4 + hf * 2 + 1] * INV_WSCALE
                                   + gx * W0f[3200 * HID + n0 + 1] + gy * W0f[3201 * HID + n0 + 1] + b0[n0 + 1];
                    *(__half2*)(smH + m * SMH_H + n0) =
                        __floats2half2_rn(__sinf(OMEGA * z0), __sinf(OMEGA * z1));
                }
    }
    NBAR_SYNC(7, 256);                               // smH visible

    // ================= Layers 1 and 2: slabs 50..57 =================
    for (int L = 0; L < 2; ++L) {
        const float* bl = L ? b2 : b1;
#pragma unroll
        for (int i = 0; i < 128; ++i) acc[i] = 0.f;
#pragma unroll 1
        for (int kb = 0; kb < 4; ++kb) {
            const int s = 50 + L * 4 + kb;
            NBAR_SYNC(1 + rR, 320);
            unsigned aAd[4], bAd[4];
            const unsigned bBufB = BBUF(rR);
#pragma unroll
            for (int mt = 0; mt < 4; ++mt) aAd[mt] = aRowH[mt] + kb * 128;
#pragma unroll
            for (int np = 0; np < 4; ++np) bAd[np] = bBufB + bRow[np];
            MMA_SLAB();
            if (s <= 54) NBAR_ARRIVE(4 + rR, 320);
            rR = (rR == 2) ? 0 : rR + 1;
        }

        NBAR_SYNC(7, 256);                           // all done reading smH
#pragma unroll
        for (int mt = 0; mt < 4; ++mt)
#pragma unroll
            for (int nt = 0; nt < 8; ++nt)
#pragma unroll
                for (int hf = 0; hf < 2; ++hf) {
                    const int m = wm * 64 + mt * 16 + lr + hf * 8;
                    const int n0 = wn * 64 + nt * 8 + lc * 2;
                    const float z0 = acc[(mt * 8 + nt) * 4 + hf * 2 + 0] * INV_WSCALE + bl[n0];
                    const float z1 = acc[(mt * 8 + nt) * 4 + hf * 2 + 1] * INV_WSCALE + bl[n0 + 1];
                    *(__half2*)(smH + m * SMH_H + n0) =
                        __floats2half2_rn(__sinf(OMEGA * z0), __sinf(OMEGA * z1));
                }
        NBAR_SYNC(7, 256);
    }

    // ================= Head: [128 x 256] @ [256 x 3] + b3 =================
    for (int idx = tid; idx < IMW * OUTC; idx += 256) {
        const int p = idx & 127, o = idx >> 7;
        float sum = b3[o];
#pragma unroll 4
        for (int k = 0; k < HID; k += 2) {
            const float2 f = __half22float2(*(const __half2*)(smH + p * SMH_H + k));
            sum += f.x * W3[k * OUTC + o] + f.y * W3[(k + 1) * OUTC + o];
        }
        out[(((size_t)bimg * OUTC + o) * IMH + hrow) * IMW + p] = sum;
    }
}

extern "C" void kernel_launch(void* const* d_in, const int* in_sizes, int n_in,
                              void* d_out, int out_size)
{
    const float* xi = (const float*)d_in[0];
    const float* W0 = (const float*)d_in[1];
    const float* b0 = (const float*)d_in[2];
    const float* W1 = (const float*)d_in[3];
    const float* b1 = (const float*)d_in[4];
    const float* W2 = (const float*)d_in[5];
    const float* b2 = (const float*)d_in[6];
    const float* W3 = (const float*)d_in[7];
    const float* b3 = (const float*)d_in[8];
    float* out = (float*)d_out;

    cudaFuncSetAttribute(nerd_fused_kernel,
                         cudaFuncAttributeMaxDynamicSharedMemorySize, SMEM_BYTES);

    prep_kernel<<<XI_BLOCKS + 464, 256>>>(xi, W0, W1, W2);
    nerd_fused_kernel<<<256, THREADS, SMEM_BYTES>>>(W0, b0, b1, b2, W3, b3, out);
}

// round 17
// speedup vs baseline: 1.0415x; 1.0415x over previous
#include <cuda_runtime.h>
#include <cuda_fp16.h>
#include <cstdint>
#include <cstddef>

// NeRD pixel decoder — fp16 mma.sync m16n8k16, ldmatrix.x4, cp.async.
// R16: M=64 per CTA, 4 warps in a 1x4 grid (warp tile 64m x 64n) -> per-MAC
// crossbar traffic IDENTICAL to the best M=128 config, but 2 independent
// CTAs/SM give decoupled barrier domains (cross-CTA latency hiding that
// single-CTA lockstep lacks; R14's 1x8 grid broke this by 8x'ing A traffic).
//   Layer 0: [64 x 3200] @ [3200 x 256] as 100 K=32 slabs (25 taps x 4 cquads)
//   Layers 1,2: [64 x 256] @ [256 x 256] as 8 K=32 slabs
//   Head: [64 x 256] @ [256 x 3] scalar
// Weights pre-scaled by 2^8 (exact); epilogue multiplies acc by 2^-8.
//
// Bank checks (ldsm 8-row wavefronts, 16B rows):
//   A/B slabs stride 40 halves = 20 words: banks {(20r+..) mod 32} distinct
//   smH stride 264 halves = 132 words (≡4 mod 32): distinct

#define FC   128
#define HID  256
#define OUTC 3
#define IMH  128
#define IMW  128
#define OMEGA 30.0f
#define THREADS 128
#define WSCALE 256.0f
#define INV_WSCALE 0.00390625f

#define SMH_H 264
#define SMA_H 40
#define SMB_H 40
#define SMH_HALF (64 * SMH_H)       // 16896
#define SMA_HALF (72 * SMA_H)       // 2880 (68 rows used; x2 alias into smH)
#define SMB_HALF (256 * SMB_H)      // 10240
#define OFF_B(st) (SMH_HALF + (st) * SMB_HALF)
#define SMEM_BYTES ((SMH_HALF + 3 * SMB_HALF) * 2)   // 95232 B -> 2 CTAs/SM

// ---- persistent scratch: pre-tiled fp16, contiguous per K=32 slab ----
__device__ __half g_xiA[2 * 4 * 132 * 132 * 32];   // [((b*4+cq)*132+hp)][wa*32+kc]
__device__ __half g_W0s[25 * 4 * 256 * 32];        // [(tap*4+cq)*256+n][kc] *2^8
__device__ __half g_W1s[8 * 256 * 32];             // [(kb*256+n)][kc]      *2^8
__device__ __half g_W2s[8 * 256 * 32];

__device__ __forceinline__ void mma16(float* c, const unsigned* a, unsigned b0, unsigned b1) {
    asm("mma.sync.aligned.m16n8k16.row.col.f32.f16.f16.f32 "
        "{%0,%1,%2,%3}, {%4,%5,%6,%7}, {%8,%9}, {%0,%1,%2,%3};"
        : "+f"(c[0]), "+f"(c[1]), "+f"(c[2]), "+f"(c[3])
        : "r"(a[0]), "r"(a[1]), "r"(a[2]), "r"(a[3]), "r"(b0), "r"(b1));
}

__device__ __forceinline__ void ldsm4(unsigned& r0, unsigned& r1, unsigned& r2,
                                      unsigned& r3, unsigned addr) {
    asm volatile("ldmatrix.sync.aligned.m8n8.x4.shared.b16 {%0,%1,%2,%3}, [%4];"
                 : "=r"(r0), "=r"(r1), "=r"(r2), "=r"(r3) : "r"(addr));
}

__device__ __forceinline__ void cpa16(unsigned dst, const void* src) {
    asm volatile("cp.async.ca.shared.global [%0], [%1], 16;" :: "r"(dst), "l"(src));
}
#define CP_COMMIT asm volatile("cp.async.commit_group;" ::: "memory")
#define CP_WAIT(n) asm volatile("cp.async.wait_group %0;" :: "n"(n) : "memory")

// ================= fused prep kernel (verified in R14) =================
#define XI_BLOCKS 1056
extern "C" __global__ void prep_kernel(const float* __restrict__ xi,
                                       const float* __restrict__ W0,
                                       const float* __restrict__ W1,
                                       const float* __restrict__ W2) {
    const int tid = threadIdx.x;
    if (blockIdx.x < XI_BLOCKS) {
        __shared__ __half smT[32][134];
        const int bi = blockIdx.x;
        const int hp = bi % 132;
        const int t  = bi / 132;
        const int cq = t & 3, b = t >> 2;
        const int h  = hp - 2;
        const bool hok = (unsigned)h < IMH;
        if (tid < 32) {
            smT[tid][0] = __half(0); smT[tid][1] = __half(0);
            smT[tid][130] = __half(0); smT[tid][131] = __half(0);
        }
        const int w = tid & 127, cl0 = tid >> 7;
        for (int cc = 0; cc < 32; cc += 2) {
            const int cl = cc + cl0;
            float v = 0.f;
            if (hok)
                v = xi[(((size_t)b * FC + cq * 32 + cl) * IMH + h) * IMW + w];
            smT[cl][w + 2] = __float2half_rn(v);
        }
        __syncthreads();
        __half2* dst2 = (__half2*)(g_xiA + ((size_t)bi) * (132 * 32));
        for (int r2 = tid; r2 < 132 * 16; r2 += 256) {
            const int kc2 = r2 & 15, wa = r2 >> 4;
            dst2[r2] = __halves2half2(smT[2 * kc2][wa], smT[2 * kc2 + 1][wa]);
        }
    } else {
        const int base = (blockIdx.x - XI_BLOCKS) * 2048;
        const int NW0 = 25 * 4 * 256 * 32;
#pragma unroll
        for (int l = 0; l < 8; ++l) {
            const int idx = base + l * 256 + tid;
            if (idx < NW0) {
                const int kc = idx & 31, n = (idx >> 5) & 255;
                const int cq = (idx >> 13) & 3, tap = idx >> 15;
                const int c = cq * 32 + kc;
                g_W0s[idx] = __float2half_rn(W0[((size_t)c * 25 + tap) * HID + n] * WSCALE);
            } else {
                int r = idx - NW0;
                if (r < 2 * 65536) {
                    const int which = r >> 16; r &= 65535;
                    const int kc = r & 31, n = (r >> 5) & 255, kb = r >> 13;
                    const int k = kb * 32 + kc;
                    const float v = (which ? W2 : W1)[(size_t)k * HID + n] * WSCALE;
                    if (which) g_W2s[r] = __float2half_rn(v);
                    else       g_W1s[r] = __float2half_rn(v);
                }
            }
        }
    }
}

// ================= main fused kernel: 128 threads, 2 CTAs/SM =================
extern "C" __global__ void __launch_bounds__(THREADS, 2)
nerd_fused_kernel(const float* __restrict__ W0f, const float* __restrict__ b0,
                  const float* __restrict__ b1, const float* __restrict__ b2,
                  const float* __restrict__ W3, const float* __restrict__ b3,
                  float* __restrict__ out)
{
    extern __shared__ __half smem[];
    __half* smH = smem;                              // [64][264]
    const unsigned sbase = (unsigned)__cvta_generic_to_shared(smem);

    const int tid  = threadIdx.x;
    const int lane = tid & 31, warp = tid >> 5;      // 4 warps, 1x4 grid
    const int wn = warp;                             // n block of 64
    const int lr = lane >> 2, lc = lane & 3;
    const int l15 = lane & 15, lhi = lane >> 4;
    const int bx = blockIdx.x;
    const int bimg  = bx >> 8;
    const int hrow  = (bx & 255) >> 1;
    const int mhalf = bx & 1;

    float acc[128];                                  // [mt4][nt8][4]
#pragma unroll
    for (int i = 0; i < 128; ++i) acc[i] = 0.f;

    // ---- per-thread address constants (bytes) ----
    unsigned aRow[4], bRow[4], aRowH[4];
#pragma unroll
    for (int mt = 0; mt < 4; ++mt) {
        aRow[mt]  = ((mt * 16 + l15) * SMA_H + lhi * 8) * 2;
        aRowH[mt] = sbase + ((mt * 16 + l15) * SMH_H + lhi * 8) * 2;
    }
#pragma unroll
    for (int np = 0; np < 4; ++np)
        bRow[np] = ((wn * 64 + np * 16 + l15) * SMB_H + lhi * 8) * 2;
    const unsigned Bbuf0 = sbase + OFF_B(0) * 2;
    const unsigned aBuf0 = sbase;
    const unsigned stB_d = ((tid >> 2) * SMB_H + (tid & 3) * 8) * 2;
    const unsigned stA_d = ((tid >> 2) * SMA_H + (tid & 3) * 8) * 2;

    // ---- staging (K=32 slabs; 128 threads) ----
    auto stage_B = [&](const __half* src, unsigned bufB) {   // 1024 chunks
        unsigned d = bufB + stB_d;
        const __half* sp = src + (size_t)tid * 8;
#pragma unroll
        for (int l = 0; l < 8; ++l) {
            cpa16(d, sp);
            d += 32 * SMB_H * 2;                     // +32 n-rows
            sp += 1024;                              // +128 chunks
        }
    };
    auto stage_A = [&](const __half* src, unsigned bufB) {   // 272 chunks
        unsigned d = bufB + stA_d;
        const __half* sp = src + (size_t)tid * 8;
        cpa16(d, sp);
        cpa16(d + 32 * SMA_H * 2, sp + 1024);
        if (tid < 16)
            cpa16(d + 64 * SMA_H * 2, sp + 2048);
    };
    auto aSrc = [&](int g) {                         // g = ph*4 + cq
        const int ph = g >> 2, cq = g & 3;
        return g_xiA + ((size_t)((bimg * 4 + cq) * 132 + hrow + ph)) * (132 * 32)
                     + (size_t)mhalf * 64 * 32;
    };
    auto bSrc0 = [&](int g, int pw) {
        const int ph = g >> 2, cq = g & 3;
        return g_W0s + ((size_t)((ph * 5 + pw) * 4 + cq)) * 8192;
    };

    // ---- prologue ----
    stage_A(aSrc(0), aBuf0); stage_B(bSrc0(0, 0), Bbuf0); CP_COMMIT;
    stage_B(bSrc0(0, 1), Bbuf0 + SMB_HALF * 2); CP_COMMIT;

    unsigned af[4][4], bf[2][4];

#define MMA_SLAB() do {                                                        \
    _Pragma("unroll") for (int kk = 0; kk < 2; ++kk) {                         \
        _Pragma("unroll") for (int mt = 0; mt < 4; ++mt)                       \
            ldsm4(af[mt][0], af[mt][1], af[mt][2], af[mt][3],                  \
                  aAd[mt] + kk * 32);                                          \
        ldsm4(bf[0][0], bf[0][1], bf[0][2], bf[0][3], bAd[0] + kk * 32);       \
        _Pragma("unroll") for (int np = 0; np < 4; ++np) {                     \
            if (np < 3) {                                                      \
                const int nb = (np + 1) & 1;                                   \
                ldsm4(bf[nb][0], bf[nb][1], bf[nb][2], bf[nb][3],              \
                      bAd[np + 1] + kk * 32);                                  \
            }                                                                  \
            const int cu = np & 1;                                             \
            _Pragma("unroll") for (int mt = 0; mt < 4; ++mt) {                 \
                mma16(&acc[(mt * 8 + 2 * np) * 4],     af[mt], bf[cu][0], bf[cu][2]); \
                mma16(&acc[(mt * 8 + 2 * np + 1) * 4], af[mt], bf[cu][1], bf[cu][3]); \
            }                                                                  \
        }                                                                      \
    } } while (0)

    // ================= Layer 0: 100 K=32 slabs =================
    int cur3 = 0, nxt3 = 2;
    for (int g = 0; g < 20; ++g) {
        const unsigned aBufB = aBuf0 + (g & 1) * (SMA_HALF * 2);
#pragma unroll 1
        for (int pw = 0; pw < 5; ++pw) {
            const int s = g * 5 + pw;
            CP_WAIT(1);
            __syncthreads();
            if (s + 2 < 100) {
                const int s2 = s + 2, gg2 = s2 / 5, pw2 = s2 - gg2 * 5;
                stage_B(bSrc0(gg2, pw2), Bbuf0 + nxt3 * (SMB_HALF * 2));
            }
            if (pw == 3 && g + 1 < 20)
                stage_A(aSrc(g + 1), aBuf0 + ((g + 1) & 1) * (SMA_HALF * 2));
            CP_COMMIT;

            unsigned aAd[4], bAd[4];
            const unsigned aPw = aBufB + pw * (SMA_H * 2);
            const unsigned bBufB = Bbuf0 + cur3 * (SMB_HALF * 2);
#pragma unroll
            for (int mt = 0; mt < 4; ++mt) aAd[mt] = aPw + aRow[mt];
#pragma unroll
            for (int np = 0; np < 4; ++np) bAd[np] = bBufB + bRow[np];
            MMA_SLAB();
            cur3 = (cur3 == 2) ? 0 : cur3 + 1;
            nxt3 = (nxt3 == 2) ? 0 : nxt3 + 1;
        }
    }
    CP_WAIT(0);
    __syncthreads();

    // ---- layer-0 epilogue: acc/256 + coords + b0, sin -> smH (fp16) ----
    {
        const float gy = -1.f + 2.f * (float)hrow * (1.f / 127.f);
#pragma unroll
        for (int mt = 0; mt < 4; ++mt)
#pragma unroll
            for (int nt = 0; nt < 8; ++nt)
#pragma unroll
                for (int hf = 0; hf < 2; ++hf) {
                    const int m = mt * 16 + lr + hf * 8;            // local 0..63
                    const int n0 = wn * 64 + nt * 8 + lc * 2;
                    const int mg = mhalf * 64 + m;
                    const float gx = -1.f + 2.f * (float)mg * (1.f / 127.f);
                    const float z0 = acc[(mt * 8 + nt) * 4 + hf * 2 + 0] * INV_WSCALE
                                   + gx * W0f[3200 * HID + n0] + gy * W0f[3201 * HID + n0] + b0[n0];
                    const float z1 = acc[(mt * 8 + nt) * 4 + hf * 2 + 1] * INV_WSCALE
                                   + gx * W0f[3200 * HID + n0 + 1] + gy * W0f[3201 * HID + n0 + 1] + b0[n0 + 1];
                    *(__half2*)(smH + m * SMH_H + n0) =
                        __floats2half2_rn(__sinf(OMEGA * z0), __sinf(OMEGA * z1));
                }
    }
    __syncthreads();

    // ================= Layers 1 and 2: 8 K=32 slabs each =====================
    for (int L = 0; L < 2; ++L) {
        const __half* Ws = L ? g_W2s : g_W1s;
        const float* bl = L ? b2 : b1;
#pragma unroll
        for (int i = 0; i < 128; ++i) acc[i] = 0.f;

        stage_B(Ws, Bbuf0); CP_COMMIT;
        stage_B(Ws + 8192, Bbuf0 + SMB_HALF * 2); CP_COMMIT;

        cur3 = 0; nxt3 = 2;
#pragma unroll 1
        for (int kb = 0; kb < 8; ++kb) {
            CP_WAIT(1);
            __syncthreads();
            if (kb + 2 < 8) stage_B(Ws + (size_t)(kb + 2) * 8192, Bbuf0 + nxt3 * (SMB_HALF * 2));
            CP_COMMIT;

            unsigned aAd[4], bAd[4];
            const unsigned bBufB = Bbuf0 + cur3 * (SMB_HALF * 2);
#pragma unroll
            for (int mt = 0; mt < 4; ++mt) aAd[mt] = aRowH[mt] + kb * 64;   // 32 halves
#pragma unroll
            for (int np = 0; np < 4; ++np) bAd[np] = bBufB + bRow[np];
            MMA_SLAB();
            cur3 = (cur3 == 2) ? 0 : cur3 + 1;
            nxt3 = (nxt3 == 2) ? 0 : nxt3 + 1;
        }
        CP_WAIT(0);
        __syncthreads();

        // epilogue: acc/256 + bl, sin -> smH
#pragma unroll
        for (int mt = 0; mt < 4; ++mt)
#pragma unroll
            for (int nt = 0; nt < 8; ++nt)
#pragma unroll
                for (int hf = 0; hf < 2; ++hf) {
                    const int m = mt * 16 + lr + hf * 8;
                    const int n0 = wn * 64 + nt * 8 + lc * 2;
                    const float z0 = acc[(mt * 8 + nt) * 4 + hf * 2 + 0] * INV_WSCALE + bl[n0];
                    const float z1 = acc[(mt * 8 + nt) * 4 + hf * 2 + 1] * INV_WSCALE + bl[n0 + 1];
                    *(__half2*)(smH + m * SMH_H + n0) =
                        __floats2half2_rn(__sinf(OMEGA * z0), __sinf(OMEGA * z1));
                }
        __syncthreads();
    }

    // ================= Head: [64 x 256] @ [256 x 3] + b3 =================
    for (int idx = tid; idx < 64 * OUTC; idx += THREADS) {
        const int p = idx & 63, o = idx >> 6;
        float sum = b3[o];
#pragma unroll 4
        for (int k = 0; k < HID; k += 2) {
            const float2 f = __half22float2(*(const __half2*)(smH + p * SMH_H + k));
            sum += f.x * W3[k * OUTC + o] + f.y * W3[(k + 1) * OUTC + o];
        }
        const int pg = mhalf * 64 + p;
        out[(((size_t)bimg * OUTC + o) * IMH + hrow) * IMW + pg] = sum;
    }
}

extern "C" void kernel_launch(void* const* d_in, const int* in_sizes, int n_in,
                              void* d_out, int out_size)
{
    const float* xi = (const float*)d_in[0];
    const float* W0 = (const float*)d_in[1];
    const float* b0 = (const float*)d_in[2];
    const float* W1 = (const float*)d_in[3];
    const float* b1 = (const float*)d_in[4];
    const float* W2 = (const float*)d_in[5];
    const float* b2 = (const float*)d_in[6];
    const float* W3 = (const float*)d_in[7];
    const float* b3 = (const float*)d_in[8];
    float* out = (float*)d_out;

    cudaFuncSetAttribute(nerd_fused_kernel,
                         cudaFuncAttributeMaxDynamicSharedMemorySize, SMEM_BYTES);

    prep_kernel<<<XI_BLOCKS + 464, 256>>>(xi, W0, W1, W2);
    nerd_fused_kernel<<<512, THREADS, SMEM_BYTES>>>(W0, b0, b1, b2, W3, b3, out);
}